// round 9
// baseline (speedup 1.0000x reference)
#include <cuda_runtime.h>
#include <math.h>

// Problem constants
#define BB   64
#define SS   512
#define DD   128
#define HH   2
#define DH   64
#define RTOT (BB*SS)          // 32768 rows
#define SZ   ((size_t)RTOT*DD) // 4194304 floats per [R,128] buffer

// ---------------- scratch (device global; no runtime allocation) ----------------
// layout (float offsets):
//  0..9  : ten [32768,128] buffers: t,v,a,q,k,vv,ctx,ot,ov,oa
//  GX    : 6 x [32768,384]
//  WIHT  : 6 x [128,384]
//  WHHT  : 6 x [128,384]
//  HSUM  : 6 x [64,128]
//  OM    : [64,384]
#define OFF_T    ((size_t)0*SZ)
#define OFF_V    ((size_t)1*SZ)
#define OFF_A    ((size_t)2*SZ)
#define OFF_Q    ((size_t)3*SZ)
#define OFF_K    ((size_t)4*SZ)
#define OFF_VV   ((size_t)5*SZ)
#define OFF_CTX  ((size_t)6*SZ)
#define OFF_OT   ((size_t)7*SZ)
#define OFF_OV   ((size_t)8*SZ)
#define OFF_OA   ((size_t)9*SZ)
#define OFF_GX   ((size_t)10*SZ)
#define GX_PER   ((size_t)RTOT*384)            // 12582912
#define OFF_WIHT (OFF_GX + (size_t)6*GX_PER)
#define OFF_WHHT (OFF_WIHT + (size_t)6*128*384)
#define OFF_HSUM (OFF_WHHT + (size_t)6*128*384)
#define OFF_OM   (OFF_HSUM + (size_t)6*64*128)
#define SCRATCH_TOTAL (OFF_OM + (size_t)64*384)   // 118,104,064 floats ~ 472MB

__device__ float g_scratch[SCRATCH_TOTAL];

// ---------------- generic GEMM: C[M,N] = A[M,K] @ W[K,N] + bias ----------------
// BM=128, BN=128 (grid.y tiles N), BK=16, 256 threads, 8x8 microtile.
// EPI==0: plain bias add.  EPI==1: bias add, per-row LayerNorm over N==128,
//         then C = beta*C + 0.5*value (beta==0 -> plain write).
template<int EPI>
__global__ __launch_bounds__(256)
void gemm128(const float* __restrict__ A, const float* __restrict__ W,
             const float* __restrict__ bias, float* __restrict__ C,
             int M, int N, int K,
             const float* __restrict__ lng, const float* __restrict__ lnb,
             float beta)
{
    __shared__ float As[128*17];
    __shared__ float Ws[16*128];
    int tid = threadIdx.x;
    int rowbase = blockIdx.x * 128;
    int nbase   = blockIdx.y * 128;
    int tx = tid & 15;        // 16 col groups of 8
    int ty = tid >> 4;        // 16 row groups of 8

    float acc[8][8];
#pragma unroll
    for (int r = 0; r < 8; r++)
#pragma unroll
        for (int c = 0; c < 8; c++) acc[r][c] = 0.f;

    for (int k0 = 0; k0 < K; k0 += 16) {
        // stage A tile [128 rows x 16 k]
#pragma unroll
        for (int p = 0; p < 8; p++) {
            int idx = tid + p*256;
            int r  = idx >> 4;
            int kk = idx & 15;
            int k  = k0 + kk;
            As[r*17 + kk] = (k < K) ? A[(size_t)(rowbase + r)*K + k] : 0.f;
        }
        // stage W tile [16 k x 128 n]
#pragma unroll
        for (int p = 0; p < 8; p++) {
            int idx = tid + p*256;
            int kk = idx >> 7;
            int n  = idx & 127;
            int k  = k0 + kk;
            Ws[kk*128 + n] = (k < K) ? W[(size_t)k*N + nbase + n] : 0.f;
        }
        __syncthreads();
#pragma unroll
        for (int kk = 0; kk < 16; kk++) {
            float4 w0 = *(const float4*)&Ws[kk*128 + tx*8];
            float4 w1 = *(const float4*)&Ws[kk*128 + tx*8 + 4];
#pragma unroll
            for (int r = 0; r < 8; r++) {
                float a = As[(ty*8 + r)*17 + kk];
                acc[r][0] += a*w0.x; acc[r][1] += a*w0.y;
                acc[r][2] += a*w0.z; acc[r][3] += a*w0.w;
                acc[r][4] += a*w1.x; acc[r][5] += a*w1.y;
                acc[r][6] += a*w1.z; acc[r][7] += a*w1.w;
            }
        }
        __syncthreads();
    }

    if (EPI == 0) {
        float4 b0 = *(const float4*)&bias[nbase + tx*8];
        float4 b1 = *(const float4*)&bias[nbase + tx*8 + 4];
#pragma unroll
        for (int r = 0; r < 8; r++) {
            int row = rowbase + ty*8 + r;
            float* Cp = C + (size_t)row*N + nbase + tx*8;
            float4 o0 = make_float4(acc[r][0]+b0.x, acc[r][1]+b0.y, acc[r][2]+b0.z, acc[r][3]+b0.w);
            float4 o1 = make_float4(acc[r][4]+b1.x, acc[r][5]+b1.y, acc[r][6]+b1.z, acc[r][7]+b1.w);
            *(float4*)Cp       = o0;
            *(float4*)(Cp + 4) = o1;
        }
    } else {
        // LayerNorm over N==128 columns (nbase==0) + scaled accumulate.
        const float inv = 1.0f / 128.0f;
#pragma unroll
        for (int r = 0; r < 8; r++) {
            float vals[8];
            float s = 0.f, s2 = 0.f;
#pragma unroll
            for (int c = 0; c < 8; c++) {
                float vv = acc[r][c] + bias[tx*8 + c];
                vals[c] = vv;
                s += vv; s2 += vv*vv;
            }
            // reduce across the 16 lanes sharing this row (lane bits 0..3)
#pragma unroll
            for (int off = 8; off >= 1; off >>= 1) {
                s  += __shfl_xor_sync(0xffffffffu, s,  off);
                s2 += __shfl_xor_sync(0xffffffffu, s2, off);
            }
            float mean = s * inv;
            float var  = s2 * inv - mean*mean;
            float rstd = rsqrtf(var + 1e-5f);
            int row = rowbase + ty*8 + r;
#pragma unroll
            for (int c = 0; c < 8; c++) {
                int col = tx*8 + c;
                float o = (vals[c] - mean) * rstd * lng[col] + lnb[col];
                size_t idx = (size_t)row*128 + col;
                if (beta == 0.f) C[idx] = 0.5f * o;
                else             C[idx] = C[idx] + 0.5f * o;
            }
        }
    }
}

// ---------------- attention core ----------------
// grid = (8 q-tiles, B*H=128), block = 256.
// ctx[b, q, h*64+dh] = sum_k (1 - softmax_k(QK^T/8)) * V
// Full 64x512 score block in smem -> exact "1 - softmax".
#define ATTN_SMEM ((2*64*68 + 64*516) * 4)

__global__ __launch_bounds__(256)
void attn_kernel(const float* __restrict__ Qb, const float* __restrict__ Kb,
                 const float* __restrict__ Vb, float* __restrict__ ctx)
{
    extern __shared__ float sm[];
    float* Qs  = sm;                 // [64][68]
    float* KVs = sm + 64*68;         // [64][68]
    float* Ssm = sm + 2*64*68;       // [64][516]

    int tid = threadIdx.x;
    int bh = blockIdx.y;
    int b = bh >> 1, h = bh & 1;
    int q0 = blockIdx.x * 64;

    size_t baseQ  = ((size_t)b*SS + q0)*DD + h*DH;
    size_t baseKV = ((size_t)b*SS)*DD + h*DH;

    // load Q tile [64,64]
#pragma unroll
    for (int p = 0; p < 16; p++) {
        int idx = tid + p*256;
        int r = idx >> 6, c = idx & 63;
        Qs[r*68 + c] = Qb[baseQ + (size_t)r*DD + c];
    }

    int tx = tid & 15;   // k / d col group (4 wide)
    int ty = tid >> 4;   // q row group (4 wide)

    // ---- scores = Q K^T / 8 ----
    for (int kt = 0; kt < 8; kt++) {
        __syncthreads();
#pragma unroll
        for (int p = 0; p < 16; p++) {
            int idx = tid + p*256;
            int r = idx >> 6, c = idx & 63;
            KVs[r*68 + c] = Kb[baseKV + (size_t)(kt*64 + r)*DD + c];
        }
        __syncthreads();
        float acc[4][4];
#pragma unroll
        for (int i = 0; i < 4; i++)
#pragma unroll
            for (int j = 0; j < 4; j++) acc[i][j] = 0.f;
#pragma unroll
        for (int d4 = 0; d4 < 16; d4++) {
            float4 qv[4], kv[4];
#pragma unroll
            for (int i = 0; i < 4; i++) qv[i] = *(const float4*)&Qs[(ty*4+i)*68 + d4*4];
#pragma unroll
            for (int j = 0; j < 4; j++) kv[j] = *(const float4*)&KVs[(tx*4+j)*68 + d4*4];
#pragma unroll
            for (int i = 0; i < 4; i++)
#pragma unroll
                for (int j = 0; j < 4; j++) {
                    acc[i][j] += qv[i].x*kv[j].x + qv[i].y*kv[j].y
                               + qv[i].z*kv[j].z + qv[i].w*kv[j].w;
                }
        }
#pragma unroll
        for (int i = 0; i < 4; i++) {
            float4 st = make_float4(acc[i][0]*0.125f, acc[i][1]*0.125f,
                                    acc[i][2]*0.125f, acc[i][3]*0.125f);
            *(float4*)&Ssm[(ty*4+i)*516 + kt*64 + tx*4] = st;
        }
    }
    __syncthreads();

    // ---- probs = 1 - softmax(scores) over k ----
    {
        int w = tid >> 5, lane = tid & 31;
        for (int rr = 0; rr < 8; rr++) {
            float* row = &Ssm[(w*8 + rr)*516];
            float m = -1e30f;
            for (int k = lane; k < 512; k += 32) m = fmaxf(m, row[k]);
#pragma unroll
            for (int off = 16; off >= 1; off >>= 1)
                m = fmaxf(m, __shfl_xor_sync(0xffffffffu, m, off));
            float s = 0.f;
            for (int k = lane; k < 512; k += 32) {
                float e = __expf(row[k] - m);
                row[k] = e;
                s += e;
            }
#pragma unroll
            for (int off = 16; off >= 1; off >>= 1)
                s += __shfl_xor_sync(0xffffffffu, s, off);
            float invs = 1.f / s;
            for (int k = lane; k < 512; k += 32)
                row[k] = 1.f - row[k] * invs;
        }
    }
    __syncthreads();

    // ---- ctx = probs @ V ----
    float acc2[4][4];
#pragma unroll
    for (int i = 0; i < 4; i++)
#pragma unroll
        for (int j = 0; j < 4; j++) acc2[i][j] = 0.f;

    for (int kt = 0; kt < 8; kt++) {
#pragma unroll
        for (int p = 0; p < 16; p++) {
            int idx = tid + p*256;
            int r = idx >> 6, c = idx & 63;
            KVs[r*68 + c] = Vb[baseKV + (size_t)(kt*64 + r)*DD + c];
        }
        __syncthreads();
#pragma unroll
        for (int k4 = 0; k4 < 16; k4++) {
            float4 pv[4], vv[4];
#pragma unroll
            for (int i = 0; i < 4; i++) pv[i] = *(const float4*)&Ssm[(ty*4+i)*516 + kt*64 + k4*4];
#pragma unroll
            for (int j = 0; j < 4; j++) vv[j] = *(const float4*)&KVs[(k4*4+j)*68 + tx*4];
#pragma unroll
            for (int i = 0; i < 4; i++) {
                acc2[i][0] += pv[i].x*vv[0].x + pv[i].y*vv[1].x + pv[i].z*vv[2].x + pv[i].w*vv[3].x;
                acc2[i][1] += pv[i].x*vv[0].y + pv[i].y*vv[1].y + pv[i].z*vv[2].y + pv[i].w*vv[3].y;
                acc2[i][2] += pv[i].x*vv[0].z + pv[i].y*vv[1].z + pv[i].z*vv[2].z + pv[i].w*vv[3].z;
                acc2[i][3] += pv[i].x*vv[0].w + pv[i].y*vv[1].w + pv[i].z*vv[2].w + pv[i].w*vv[3].w;
            }
        }
        __syncthreads();
    }
#pragma unroll
    for (int i = 0; i < 4; i++) {
        size_t idx = ((size_t)b*SS + q0 + ty*4 + i)*DD + h*DH + tx*4;
        *(float4*)&ctx[idx] = make_float4(acc2[i][0], acc2[i][1], acc2[i][2], acc2[i][3]);
    }
}

// ---------------- weight transpose for GRU (Wih/Whh [384,128] -> [128,384]) ----
__global__ void transpose_w_kernel(const float* __restrict__ gWih,
                                   const float* __restrict__ gWhh,
                                   float* __restrict__ WihT, float* __restrict__ WhhT)
{
    int m = blockIdx.x;                 // 0..11
    const float* src = (m < 6 ? gWih : gWhh) + (size_t)(m % 6)*384*128;
    float*       dst = (m < 6 ? WihT : WhhT) + (size_t)(m % 6)*128*384;
    for (int idx = threadIdx.x; idx < 128*384; idx += blockDim.x) {
        int k = idx / 384, n = idx % 384;
        dst[idx] = src[(size_t)n*128 + k];
    }
}

// ---------------- GRU recurrence ----------------
// grid = 384 (dir6*64 + b), block = 384. Each thread owns one output gate
// column j; its Whh column (128 floats) lives in registers.
__global__ __launch_bounds__(384)
void gru_kernel(const float* __restrict__ WhhT, const float* __restrict__ gbhh,
                const float* __restrict__ gx, float* __restrict__ hsum)
{
    int dir6 = blockIdx.x >> 6;
    int b    = blockIdx.x & 63;
    int j    = threadIdx.x;

    const float* wp = WhhT + (size_t)dir6*128*384 + j;
    float w[128];
#pragma unroll
    for (int k = 0; k < 128; k++) w[k] = wp[(size_t)k*384];
    float bh = gbhh[dir6*384 + j];

    __shared__ float h[128];
    __shared__ float gh[384];
    __shared__ float hs[128];
    if (j < 128) { h[j] = 0.f; hs[j] = 0.f; }

    const float* gxb = gx + ((size_t)(dir6*64 + b))*SS*384;
    int rev = dir6 & 1;

    for (int step = 0; step < SS; step++) {
        int t = rev ? (SS - 1 - step) : step;
        __syncthreads();          // h for this step is ready
        float acc = bh;
#pragma unroll
        for (int k4 = 0; k4 < 32; k4++) {
            float4 hv = *(const float4*)&h[k4*4];
            acc += w[k4*4+0]*hv.x + w[k4*4+1]*hv.y
                 + w[k4*4+2]*hv.z + w[k4*4+3]*hv.w;
        }
        gh[j] = acc;
        __syncthreads();          // gh complete
        if (j < 128) {
            const float* gr = gxb + (size_t)t*384;
            float r  = 1.f / (1.f + __expf(-(gr[j]       + gh[j])));
            float z  = 1.f / (1.f + __expf(-(gr[128 + j] + gh[128 + j])));
            float n  = tanhf(gr[256 + j] + r * gh[256 + j]);
            float hn = (1.f - z)*n + z*h[j];
            h[j]  = hn;
            hs[j] += hn;
        }
    }
    __syncthreads();
    if (j < 128) hsum[((size_t)dir6*64 + b)*128 + j] = hs[j];
}

// ---------------- combine h-sums -> pooled features [64,384] ----------------
__global__ void combine_kernel(const float* __restrict__ hsum, float* __restrict__ om)
{
    int b = blockIdx.x;
    int j = threadIdx.x;          // 0..383
    int seg = j >> 7, i = j & 127;
    // first384 = [t_fwd(0), t_bwd(1), v_fwd(2)]; last384 = [v_bwd(3), a_fwd(4), a_bwd(5)]
    float v = hsum[((size_t)seg*64 + b)*128 + i] + hsum[((size_t)(seg+3)*64 + b)*128 + i];
    om[b*384 + j] = v * (0.5f / 512.0f);
}

// ---------------- head: Linear(384,256)->BN(eval)->ReLU6->Linear(256,8) -------
__global__ __launch_bounds__(256)
void head_kernel(const float* __restrict__ om,
                 const float* __restrict__ fW1, const float* __restrict__ fb1,
                 const float* __restrict__ bng, const float* __restrict__ bnb,
                 const float* __restrict__ fW2, const float* __restrict__ fb2,
                 float* __restrict__ out)
{
    __shared__ float oms[384];
    __shared__ float hsh[256];
    int b = blockIdx.x, tid = threadIdx.x;
    for (int k = tid; k < 384; k += 256) oms[k] = om[b*384 + k];
    __syncthreads();
    float acc = fb1[tid];
    for (int k = 0; k < 384; k++) acc += oms[k] * fW1[(size_t)k*256 + tid];
    float scale = rsqrtf(1.0f + 1e-5f);
    float hv = acc * scale * bng[tid] + bnb[tid];
    hv = fminf(fmaxf(hv, 0.f), 6.f);
    hsh[tid] = hv;
    __syncthreads();
    if (tid < 8) {
        float a2 = fb2[tid];
        for (int k = 0; k < 256; k++) a2 += hsh[k] * fW2[k*8 + tid];
        out[b*8 + tid] = a2;
    }
}

// ---------------- host launcher ----------------
extern "C" void kernel_launch(void* const* d_in, const int* in_sizes, int n_in,
                              void* d_out, int out_size)
{
    (void)in_sizes; (void)n_in; (void)out_size;
    const float* text   = (const float*)d_in[0];
    const float* visual = (const float*)d_in[1];
    const float* audio  = (const float*)d_in[2];
    const float* fc1W = (const float*)d_in[3];
    const float* fc1b = (const float*)d_in[4];
    const float* fc2W = (const float*)d_in[5];
    const float* fc2b = (const float*)d_in[6];
    const float* fc3W = (const float*)d_in[7];
    const float* fc3b = (const float*)d_in[8];
    const float* Wq = (const float*)d_in[9];
    const float* bq = (const float*)d_in[10];
    const float* Wk = (const float*)d_in[11];
    const float* bk = (const float*)d_in[12];
    const float* Wv = (const float*)d_in[13];
    const float* bv = (const float*)d_in[14];
    const float* Wd = (const float*)d_in[15];
    const float* bd = (const float*)d_in[16];
    const float* lng = (const float*)d_in[17];
    const float* lnb = (const float*)d_in[18];
    const float* gWih = (const float*)d_in[19];
    const float* gWhh = (const float*)d_in[20];
    const float* gbih = (const float*)d_in[21];
    const float* gbhh = (const float*)d_in[22];
    const float* fW1 = (const float*)d_in[23];
    const float* fb1 = (const float*)d_in[24];
    const float* bng = (const float*)d_in[25];
    const float* bnb = (const float*)d_in[26];
    const float* fW2 = (const float*)d_in[27];
    const float* fb2 = (const float*)d_in[28];
    float* out = (float*)d_out;

    float* S = nullptr;
    cudaGetSymbolAddress((void**)&S, g_scratch);

    float* tb   = S + OFF_T;
    float* vbuf = S + OFF_V;
    float* abuf = S + OFF_A;
    float* qb   = S + OFF_Q;
    float* kb   = S + OFF_K;
    float* vvb  = S + OFF_VV;
    float* ctx  = S + OFF_CTX;
    float* ot   = S + OFF_OT;
    float* ov   = S + OFF_OV;
    float* oa   = S + OFF_OA;

    cudaFuncSetAttribute(attn_kernel,
                         cudaFuncAttributeMaxDynamicSharedMemorySize, ATTN_SMEM);

    dim3 blk(256);
    dim3 g1(RTOT/128, 1);

    // GRU weight transposes
    transpose_w_kernel<<<12, 256>>>(gWih, gWhh, S + OFF_WIHT, S + OFF_WHHT);

    // input projections
    gemm128<0><<<g1, blk>>>(text,   fc1W, fc1b, tb,   RTOT, 128, 300, nullptr, nullptr, 0.f);
    gemm128<0><<<g1, blk>>>(visual, fc2W, fc2b, vbuf, RTOT, 128, 35,  nullptr, nullptr, 0.f);
    gemm128<0><<<g1, blk>>>(audio,  fc3W, fc3b, abuf, RTOT, 128, 74,  nullptr, nullptr, 0.f);

    // six attention units
    const float* qs[6]  = {tb,   abuf, tb,   vbuf, vbuf, abuf};
    const float* ks2[6] = {abuf, tb,   vbuf, tb,   abuf, vbuf};
    float* accb[6]      = {oa,   ot,   ov,   ot,   oa,   ov};
    const float betas[6] = {0.f, 0.f, 0.f, 1.f, 1.f, 1.f};

    for (int i = 0; i < 6; i++) {
        gemm128<0><<<g1, blk>>>(qs[i],  Wq + (size_t)i*16384, bq + i*128, qb,  RTOT, 128, 128, nullptr, nullptr, 0.f);
        gemm128<0><<<g1, blk>>>(ks2[i], Wk + (size_t)i*16384, bk + i*128, kb,  RTOT, 128, 128, nullptr, nullptr, 0.f);
        gemm128<0><<<g1, blk>>>(ks2[i], Wv + (size_t)i*16384, bv + i*128, vvb, RTOT, 128, 128, nullptr, nullptr, 0.f);
        attn_kernel<<<dim3(8, 128), blk, ATTN_SMEM>>>(qb, kb, vvb, ctx);
        gemm128<1><<<g1, blk>>>(ctx, Wd + (size_t)i*16384, bd + i*128, accb[i],
                                RTOT, 128, 128, lng + i*128, lnb + i*128, betas[i]);
    }

    // GRU input-gate precompute: gx = x @ Wih^T + bih  ([32768,384] per direction)
    const float* xs[3] = {ot, ov, oa};
    for (int g = 0; g < 3; g++) {
        for (int d = 0; d < 2; d++) {
            int dir6 = g*2 + d;
            gemm128<0><<<dim3(RTOT/128, 3), blk>>>(
                xs[g], S + OFF_WIHT + (size_t)dir6*128*384, gbih + dir6*384,
                S + OFF_GX + (size_t)dir6*GX_PER,
                RTOT, 384, 128, nullptr, nullptr, 0.f);
        }
    }

    // recurrence (384 independent chains), then pooling + head
    gru_kernel<<<384, 384>>>(S + OFF_WHHT, gbhh, S + OFF_GX, S + OFF_HSUM);
    combine_kernel<<<64, 384>>>(S + OFF_HSUM, S + OFF_OM);
    head_kernel<<<64, 256>>>(S + OFF_OM, fW1, fb1, bng, bnb, fW2, fb2, out);
}

// round 10
// speedup vs baseline: 1.8403x; 1.8403x over previous
#include <cuda_runtime.h>
#include <math.h>

// Problem constants
#define BB   64
#define SS   512
#define DD   128
#define DH   64
#define RTOT (BB*SS)                    // 32768 rows

static constexpr size_t SZ       = (size_t)RTOT * DD;      // 4194304 floats
static constexpr size_t OFF_T    = 0;                      // t,v,a at 0,1,2
static constexpr size_t OFF_QKV  = 3*SZ;                   // 18 buffers (unit*3 + {q,k,v})
static constexpr size_t OFF_CTX  = 21*SZ;                  // 6 buffers
static constexpr size_t OFF_OUT3 = 27*SZ;                  // ot, ov, oa
static constexpr size_t OFF_VSUM = 30*SZ;                  // [6][64][2][64]
static constexpr size_t OFF_GX   = OFF_VSUM + 49152;
static constexpr size_t GX_PER   = (size_t)RTOT * 384;     // 12582912
static constexpr size_t OFF_WIHT = OFF_GX + 6*GX_PER;      // 6 x [128][384]
static constexpr size_t OFF_WHHT = OFF_WIHT + 6*49152;
static constexpr size_t OFF_HSUM = OFF_WHHT + 6*49152;     // [6][64][128]
static constexpr size_t OFF_OM   = OFF_HSUM + 49152;       // [64][384]
static constexpr size_t SCRATCH_TOTAL = OFF_OM + 24576;

__device__ float g_scratch[SCRATCH_TOTAL];

// ---------------- packed fp32x2 FMA (FFMA2; ptxas never auto-generates) -------
__device__ __forceinline__ void ffma2(float2& d, float2 a, float2 b) {
    asm("fma.rn.f32x2 %0, %1, %2, %0;"
        : "+l"(reinterpret_cast<unsigned long long&>(d))
        : "l"(reinterpret_cast<unsigned long long&>(a)),
          "l"(reinterpret_cast<unsigned long long&>(b)));
}
__device__ __forceinline__ float2 dup2(float a) { return make_float2(a, a); }

// ---------------- shared GEMM core: 128x128 tile, BK=16, 256 thr, 8x8 micro ---
// acc[r][c] is float2 covering output cols tx*8 + 2c, +1.
__device__ __forceinline__ void gemm_core(
    const float* __restrict__ Arow,   // A + rowbase*K (row stride == K)
    int K,
    const float* __restrict__ Wp,     // W + nbase     (row stride == ldw)
    int ldw,
    float2 (&acc)[8][4],
    float* As, float* Ws, int tid)
{
    int tx = tid & 15, ty = tid >> 4;
    for (int k0 = 0; k0 < K; k0 += 16) {
#pragma unroll
        for (int p = 0; p < 8; p++) {
            int idx = tid + p*256;
            int r = idx >> 4, kk = idx & 15;
            int k = k0 + kk;
            As[r*17 + kk] = (k < K) ? Arow[(size_t)r*K + k] : 0.f;
        }
#pragma unroll
        for (int p = 0; p < 8; p++) {
            int idx = tid + p*256;
            int kk = idx >> 7, n = idx & 127;
            int k = k0 + kk;
            Ws[kk*128 + n] = (k < K) ? Wp[(size_t)k*ldw + n] : 0.f;
        }
        __syncthreads();
#pragma unroll
        for (int kk = 0; kk < 16; kk++) {
            float4 w0 = *(const float4*)&Ws[kk*128 + tx*8];
            float4 w1 = *(const float4*)&Ws[kk*128 + tx*8 + 4];
            float2 wv0 = make_float2(w0.x, w0.y);
            float2 wv1 = make_float2(w0.z, w0.w);
            float2 wv2 = make_float2(w1.x, w1.y);
            float2 wv3 = make_float2(w1.z, w1.w);
#pragma unroll
            for (int r = 0; r < 8; r++) {
                float2 aa = dup2(As[(ty*8 + r)*17 + kk]);
                ffma2(acc[r][0], aa, wv0);
                ffma2(acc[r][1], aa, wv1);
                ffma2(acc[r][2], aa, wv2);
                ffma2(acc[r][3], aa, wv3);
            }
        }
        __syncthreads();
    }
}

__device__ __forceinline__ void epi_plain(
    float2 (&acc)[8][4], const float* __restrict__ bias,
    float* __restrict__ C, int ldc, int rowbase, int nbase, int tid)
{
    int tx = tid & 15, ty = tid >> 4;
    float4 b0 = *(const float4*)&bias[nbase + tx*8];
    float4 b1 = *(const float4*)&bias[nbase + tx*8 + 4];
#pragma unroll
    for (int r = 0; r < 8; r++) {
        int row = rowbase + ty*8 + r;
        float* Cp = C + (size_t)row*ldc + nbase + tx*8;
        float4 o0 = make_float4(acc[r][0].x + b0.x, acc[r][0].y + b0.y,
                                acc[r][1].x + b0.z, acc[r][1].y + b0.w);
        float4 o1 = make_float4(acc[r][2].x + b1.x, acc[r][2].y + b1.y,
                                acc[r][3].x + b1.z, acc[r][3].y + b1.w);
        *(float4*)Cp       = o0;
        *(float4*)(Cp + 4) = o1;
    }
}

// ---------------- input projection GEMMs ----------------
__global__ __launch_bounds__(256, 2)
void proj_gemm(const float* __restrict__ A, const float* __restrict__ W,
               const float* __restrict__ bias, int K, int dst)
{
    __shared__ float As[128*17];
    __shared__ float Ws[16*128];
    int tid = threadIdx.x;
    int rowbase = blockIdx.x * 128;
    float2 acc[8][4];
#pragma unroll
    for (int r = 0; r < 8; r++)
#pragma unroll
        for (int c = 0; c < 4; c++) acc[r][c] = make_float2(0.f, 0.f);
    gemm_core(A + (size_t)rowbase*K, K, W, 128, acc, As, Ws, tid);
    epi_plain(acc, bias, g_scratch + OFF_T + (size_t)dst*SZ, 128, rowbase, 0, tid);
}

// ---------------- batched QKV GEMMs (z = unit*3 + which) ----------------
__global__ __launch_bounds__(256, 2)
void qkv_gemm(const float* __restrict__ Wq, const float* __restrict__ Wk,
              const float* __restrict__ Wv, const float* __restrict__ bq,
              const float* __restrict__ bk, const float* __restrict__ bv)
{
    __shared__ float As[128*17];
    __shared__ float Ws[16*128];
    const int qsel[6] = {0,2,0,1,1,2};
    const int ksel[6] = {2,0,1,0,2,1};
    int tid = threadIdx.x;
    int z = blockIdx.z;
    int unit = z / 3, which = z % 3;
    int src = (which == 0) ? qsel[unit] : ksel[unit];
    const float* A = g_scratch + OFF_T + (size_t)src*SZ;
    const float* W = ((which == 0) ? Wq : (which == 1) ? Wk : Wv) + (size_t)unit*16384;
    const float* b = ((which == 0) ? bq : (which == 1) ? bk : bv) + unit*128;
    float* C = g_scratch + OFF_QKV + (size_t)z*SZ;
    int rowbase = blockIdx.x * 128;
    float2 acc[8][4];
#pragma unroll
    for (int r = 0; r < 8; r++)
#pragma unroll
        for (int c = 0; c < 4; c++) acc[r][c] = make_float2(0.f, 0.f);
    gemm_core(A + (size_t)rowbase*128, 128, W, 128, acc, As, Ws, tid);
    epi_plain(acc, b, C, 128, rowbase, 0, tid);
}

// ---------------- V column sums (for ctx = Vsum - softmax@V) ----------------
__global__ void vsum_kernel()
{
    int b = blockIdx.x, h = blockIdx.y, u = blockIdx.z, d = threadIdx.x;
    const float* V = g_scratch + OFF_QKV + (size_t)(u*3 + 2)*SZ
                   + (size_t)b*SS*DD + h*DH + d;
    float s = 0.f;
#pragma unroll 8
    for (int k = 0; k < SS; k++) s += V[(size_t)k*DD];
    g_scratch[OFF_VSUM + (((size_t)u*64 + b)*2 + h)*64 + d] = s;
}

// ---------------- batched flash attention ----------------
// grid = (8 q-tiles, B*H=128, 6 units), block = 256, dyn smem = 4*64*68*4 B.
// ctx = Vsum - softmax(QK^T/8)@V  (exactly (1 - softmax)@V).
#define ATTN_SMEM (4*64*68*4)

__global__ __launch_bounds__(256, 2)
void attn_flash()
{
    extern __shared__ float sm[];
    float* Qs = sm;              // [64][68]  (row-major, q rows)
    float* Ks = sm + 64*68;      // [64][68]  TRANSPOSED: Ks[d][k]
    float* Vs = sm + 2*64*68;    // [64][68]  (row = k)
    float* Ps = sm + 3*64*68;    // [64][68]  (row = q, col = k)

    int tid = threadIdx.x;
    int u = blockIdx.z;
    int bh = blockIdx.y;
    int b = bh >> 1, h = bh & 1;
    int q0 = blockIdx.x * 64;

    const float* Qb = g_scratch + OFF_QKV + (size_t)(u*3 + 0)*SZ;
    const float* Kb = g_scratch + OFF_QKV + (size_t)(u*3 + 1)*SZ;
    const float* Vb = g_scratch + OFF_QKV + (size_t)(u*3 + 2)*SZ;
    size_t baseQ  = ((size_t)b*SS + q0)*DD + h*DH;
    size_t baseKV = ((size_t)b*SS)*DD + h*DH;

#pragma unroll
    for (int p = 0; p < 16; p++) {
        int idx = tid + p*256;
        int r = idx >> 6, c = idx & 63;
        Qs[r*68 + c] = Qb[baseQ + (size_t)r*DD + c];
    }

    int tx = tid & 15;   // 4 output d-cols / 4 k-cols
    int ty = tid >> 4;   // 4 q rows

    float2 oacc[4][2];
    float m[4], l[4];
#pragma unroll
    for (int i = 0; i < 4; i++) {
        oacc[i][0] = make_float2(0.f, 0.f);
        oacc[i][1] = make_float2(0.f, 0.f);
        m[i] = -1e30f; l[i] = 0.f;
    }

    for (int kt = 0; kt < 8; kt++) {
        __syncthreads();                       // prev PV done with Vs/Ps
#pragma unroll
        for (int p = 0; p < 16; p++) {
            int idx = tid + p*256;
            int r = idx >> 6, c = idx & 63;
            size_t g = baseKV + (size_t)(kt*64 + r)*DD + c;
            Ks[c*68 + r] = Kb[g];              // transposed store
            Vs[r*68 + c] = Vb[g];
        }
        __syncthreads();

        // scores: s2[i][0]=(j0,j1), s2[i][1]=(j2,j3)
        float2 s2[4][2];
#pragma unroll
        for (int i = 0; i < 4; i++) { s2[i][0] = make_float2(0.f,0.f); s2[i][1] = make_float2(0.f,0.f); }
#pragma unroll 8
        for (int d = 0; d < 64; d++) {
            float4 k4 = *(const float4*)&Ks[d*68 + tx*4];
            float2 ka = make_float2(k4.x, k4.y);
            float2 kb2 = make_float2(k4.z, k4.w);
#pragma unroll
            for (int i = 0; i < 4; i++) {
                float2 qq = dup2(Qs[(ty*4 + i)*68 + d]);
                ffma2(s2[i][0], qq, ka);
                ffma2(s2[i][1], qq, kb2);
            }
        }

        // online softmax update + stash P
#pragma unroll
        for (int i = 0; i < 4; i++) {
            float s0 = s2[i][0].x * 0.125f;
            float s1 = s2[i][0].y * 0.125f;
            float s2v = s2[i][1].x * 0.125f;
            float s3 = s2[i][1].y * 0.125f;
            float tm = fmaxf(fmaxf(s0, s1), fmaxf(s2v, s3));
#pragma unroll
            for (int off = 8; off >= 1; off >>= 1)
                tm = fmaxf(tm, __shfl_xor_sync(0xffffffffu, tm, off));
            float mn = fmaxf(m[i], tm);
            float corr = __expf(m[i] - mn);
            float p0 = __expf(s0 - mn);
            float p1 = __expf(s1 - mn);
            float p2 = __expf(s2v - mn);
            float p3 = __expf(s3 - mn);
            float ps = p0 + p1 + p2 + p3;
#pragma unroll
            for (int off = 8; off >= 1; off >>= 1)
                ps += __shfl_xor_sync(0xffffffffu, ps, off);
            l[i] = l[i]*corr + ps;
            oacc[i][0].x *= corr; oacc[i][0].y *= corr;
            oacc[i][1].x *= corr; oacc[i][1].y *= corr;
            m[i] = mn;
            *(float4*)&Ps[(ty*4 + i)*68 + tx*4] = make_float4(p0, p1, p2, p3);
        }
        __syncthreads();                       // Ps visible

        // PV: oacc[i] += P[row i] @ Vtile
#pragma unroll 4
        for (int k4i = 0; k4i < 16; k4i++) {
            float4 p4[4];
#pragma unroll
            for (int i = 0; i < 4; i++)
                p4[i] = *(const float4*)&Ps[(ty*4 + i)*68 + k4i*4];
#pragma unroll
            for (int kk = 0; kk < 4; kk++) {
                float4 v4 = *(const float4*)&Vs[(k4i*4 + kk)*68 + tx*4];
                float2 va = make_float2(v4.x, v4.y);
                float2 vb2 = make_float2(v4.z, v4.w);
#pragma unroll
                for (int i = 0; i < 4; i++) {
                    float pk = (kk == 0) ? p4[i].x : (kk == 1) ? p4[i].y
                             : (kk == 2) ? p4[i].z : p4[i].w;
                    float2 pp = dup2(pk);
                    ffma2(oacc[i][0], pp, va);
                    ffma2(oacc[i][1], pp, vb2);
                }
            }
        }
    }

    float4 vs4 = *(const float4*)&g_scratch[OFF_VSUM + (((size_t)u*64 + b)*2 + h)*64 + tx*4];
    float* Cb = g_scratch + OFF_CTX + (size_t)u*SZ;
#pragma unroll
    for (int i = 0; i < 4; i++) {
        float inv = 1.f / l[i];
        size_t idx = ((size_t)b*SS + q0 + ty*4 + i)*DD + h*DH + tx*4;
        float4 o;
        o.x = vs4.x - oacc[i][0].x * inv;
        o.y = vs4.y - oacc[i][0].y * inv;
        o.z = vs4.z - oacc[i][1].x * inv;
        o.w = vs4.w - oacc[i][1].y * inv;
        *(float4*)&Cb[idx] = o;
    }
}

// ---------------- batched out-proj + LayerNorm + 0.5*accumulate --------------
// phase 0: units 0,1,2 (beta=0); phase 1: units 3,4,5 (beta=1)
__global__ __launch_bounds__(256, 2)
void epi_gemm(const float* __restrict__ Wd, const float* __restrict__ bd,
              const float* __restrict__ lng, const float* __restrict__ lnb,
              int phase)
{
    __shared__ float As[128*17];
    __shared__ float Ws[16*128];
    const int accsel[6] = {2,0,1,0,2,1};   // -> {ot,ov,oa} index
    int tid = threadIdx.x;
    int unit = phase*3 + blockIdx.z;
    const float* A = g_scratch + OFF_CTX + (size_t)unit*SZ;
    float* C = g_scratch + OFF_OUT3 + (size_t)accsel[unit]*SZ;
    const float* bias = bd + unit*128;
    const float* lg = lng + unit*128;
    const float* lb = lnb + unit*128;
    int rowbase = blockIdx.x * 128;

    float2 acc[8][4];
#pragma unroll
    for (int r = 0; r < 8; r++)
#pragma unroll
        for (int c = 0; c < 4; c++) acc[r][c] = make_float2(0.f, 0.f);
    gemm_core(A + (size_t)rowbase*128, 128, Wd + (size_t)unit*16384, 128, acc, As, Ws, tid);

    int tx = tid & 15, ty = tid >> 4;
    const float inv = 1.0f / 128.0f;
#pragma unroll
    for (int r = 0; r < 8; r++) {
        float vals[8];
        float s = 0.f, s2 = 0.f;
#pragma unroll
        for (int c = 0; c < 8; c++) {
            float2 a2 = acc[r][c >> 1];
            float vv = ((c & 1) ? a2.y : a2.x) + bias[tx*8 + c];
            vals[c] = vv; s += vv; s2 += vv*vv;
        }
#pragma unroll
        for (int off = 8; off >= 1; off >>= 1) {
            s  += __shfl_xor_sync(0xffffffffu, s,  off);
            s2 += __shfl_xor_sync(0xffffffffu, s2, off);
        }
        float mean = s * inv;
        float var  = s2 * inv - mean*mean;
        float rstd = rsqrtf(var + 1e-5f);
        int row = rowbase + ty*8 + r;
#pragma unroll
        for (int c = 0; c < 8; c++) {
            int col = tx*8 + c;
            float o = (vals[c] - mean) * rstd * lg[col] + lb[col];
            size_t idx = (size_t)row*128 + col;
            if (phase == 0) C[idx] = 0.5f * o;
            else            C[idx] = C[idx] + 0.5f * o;
        }
    }
}

// ---------------- batched GRU input-gate GEMMs (z = dir6) ----------------
__global__ __launch_bounds__(256, 2)
void gx_gemm(const float* __restrict__ gbih)
{
    __shared__ float As[128*17];
    __shared__ float Ws[16*128];
    int tid = threadIdx.x;
    int z = blockIdx.z;                         // dir6
    const float* A = g_scratch + OFF_OUT3 + (size_t)(z >> 1)*SZ;
    const float* Wp = g_scratch + OFF_WIHT + (size_t)z*49152;
    float* C = g_scratch + OFF_GX + (size_t)z*GX_PER;
    int rowbase = blockIdx.x * 128;
    int nbase   = blockIdx.y * 128;

    float2 acc[8][4];
#pragma unroll
    for (int r = 0; r < 8; r++)
#pragma unroll
        for (int c = 0; c < 4; c++) acc[r][c] = make_float2(0.f, 0.f);
    gemm_core(A + (size_t)rowbase*128, 128, Wp + nbase, 384, acc, As, Ws, tid);
    epi_plain(acc, gbih + z*384, C, 384, rowbase, nbase, tid);
}

// ---------------- GRU weight transposes ----------------
__global__ void transpose_w_kernel(const float* __restrict__ gWih,
                                   const float* __restrict__ gWhh)
{
    int mIdx = blockIdx.x;                 // 0..11
    const float* src = (mIdx < 6 ? gWih : gWhh) + (size_t)(mIdx % 6)*384*128;
    float* dst = g_scratch + (mIdx < 6 ? OFF_WIHT : OFF_WHHT) + (size_t)(mIdx % 6)*49152;
    for (int idx = threadIdx.x; idx < 128*384; idx += blockDim.x) {
        int k = idx / 384, n = idx % 384;
        dst[idx] = src[(size_t)n*128 + k];
    }
}

// ---------------- GRU recurrence (384 chains) ----------------
__global__ __launch_bounds__(384)
void gru_kernel(const float* __restrict__ gbhh)
{
    int dir6 = blockIdx.x >> 6;
    int b    = blockIdx.x & 63;
    int j    = threadIdx.x;

    const float* wp = g_scratch + OFF_WHHT + (size_t)dir6*49152 + j;
    float2 w2[64];
#pragma unroll
    for (int k = 0; k < 64; k++)
        w2[k] = make_float2(wp[(size_t)(2*k)*384], wp[(size_t)(2*k + 1)*384]);
    float bh = gbhh[dir6*384 + j];

    __shared__ float h[128];
    __shared__ float gh[384];
    __shared__ float gxs[384];
    __shared__ float hs[128];
    if (j < 128) { h[j] = 0.f; hs[j] = 0.f; }

    const float* gxb = g_scratch + OFF_GX + (size_t)dir6*GX_PER + (size_t)b*SS*384;
    int rev = dir6 & 1;
    const float2* h2 = (const float2*)h;

    for (int step = 0; step < SS; step++) {
        int t = rev ? (SS - 1 - step) : step;
        float gxv = gxb[(size_t)t*384 + j];     // prefetch (latency hidden by matvec)
        __syncthreads();                        // h ready; prev gxs reads done
        gxs[j] = gxv;
        float2 acc = make_float2(0.f, 0.f);
#pragma unroll
        for (int k = 0; k < 64; k++) ffma2(acc, w2[k], h2[k]);
        gh[j] = acc.x + acc.y + bh;
        __syncthreads();                        // gh + gxs complete
        if (j < 128) {
            float r  = 1.f / (1.f + __expf(-(gxs[j]       + gh[j])));
            float z  = 1.f / (1.f + __expf(-(gxs[128 + j] + gh[128 + j])));
            float n  = tanhf(gxs[256 + j] + r * gh[256 + j]);
            float hn = (1.f - z)*n + z*h[j];
            h[j]  = hn;
            hs[j] += hn;
        }
    }
    __syncthreads();
    if (j < 128) g_scratch[OFF_HSUM + ((size_t)dir6*64 + b)*128 + j] = hs[j];
}

// ---------------- combine h-sums -> pooled features [64,384] ----------------
__global__ void combine_kernel()
{
    int b = blockIdx.x;
    int j = threadIdx.x;          // 0..383
    int seg = j >> 7, i = j & 127;
    float v = g_scratch[OFF_HSUM + ((size_t)seg*64 + b)*128 + i]
            + g_scratch[OFF_HSUM + ((size_t)(seg + 3)*64 + b)*128 + i];
    g_scratch[OFF_OM + (size_t)b*384 + j] = v * (0.5f / 512.0f);
}

// ---------------- head: Linear(384,256)->BN(eval)->ReLU6->Linear(256,8) ------
__global__ __launch_bounds__(256)
void head_kernel(const float* __restrict__ fW1, const float* __restrict__ fb1,
                 const float* __restrict__ bng, const float* __restrict__ bnb,
                 const float* __restrict__ fW2, const float* __restrict__ fb2,
                 float* __restrict__ out)
{
    __shared__ float oms[384];
    __shared__ float hsh[256];
    int b = blockIdx.x, tid = threadIdx.x;
    for (int k = tid; k < 384; k += 256) oms[k] = g_scratch[OFF_OM + (size_t)b*384 + k];
    __syncthreads();
    float acc = fb1[tid];
    for (int k = 0; k < 384; k++) acc += oms[k] * fW1[(size_t)k*256 + tid];
    float scale = rsqrtf(1.0f + 1e-5f);
    float hv = acc * scale * bng[tid] + bnb[tid];
    hv = fminf(fmaxf(hv, 0.f), 6.f);
    hsh[tid] = hv;
    __syncthreads();
    if (tid < 8) {
        float a2 = fb2[tid];
        for (int k = 0; k < 256; k++) a2 += hsh[k] * fW2[k*8 + tid];
        out[b*8 + tid] = a2;
    }
}

// ---------------- host launcher ----------------
extern "C" void kernel_launch(void* const* d_in, const int* in_sizes, int n_in,
                              void* d_out, int out_size)
{
    (void)in_sizes; (void)n_in; (void)out_size;
    const float* text   = (const float*)d_in[0];
    const float* visual = (const float*)d_in[1];
    const float* audio  = (const float*)d_in[2];
    const float* fc1W = (const float*)d_in[3];
    const float* fc1b = (const float*)d_in[4];
    const float* fc2W = (const float*)d_in[5];
    const float* fc2b = (const float*)d_in[6];
    const float* fc3W = (const float*)d_in[7];
    const float* fc3b = (const float*)d_in[8];
    const float* Wq = (const float*)d_in[9];
    const float* bq = (const float*)d_in[10];
    const float* Wk = (const float*)d_in[11];
    const float* bk = (const float*)d_in[12];
    const float* Wv = (const float*)d_in[13];
    const float* bv = (const float*)d_in[14];
    const float* Wd = (const float*)d_in[15];
    const float* bd = (const float*)d_in[16];
    const float* lng = (const float*)d_in[17];
    const float* lnb = (const float*)d_in[18];
    const float* gWih = (const float*)d_in[19];
    const float* gWhh = (const float*)d_in[20];
    const float* gbih = (const float*)d_in[21];
    const float* gbhh = (const float*)d_in[22];
    const float* fW1 = (const float*)d_in[23];
    const float* fb1 = (const float*)d_in[24];
    const float* bng = (const float*)d_in[25];
    const float* bnb = (const float*)d_in[26];
    const float* fW2 = (const float*)d_in[27];
    const float* fb2 = (const float*)d_in[28];
    float* out = (float*)d_out;

    cudaFuncSetAttribute(attn_flash,
                         cudaFuncAttributeMaxDynamicSharedMemorySize, ATTN_SMEM);

    dim3 blk(256);

    // GRU weight transposes (independent; overlaps downstream launches' tails)
    transpose_w_kernel<<<12, 256>>>(gWih, gWhh);

    // input projections into t,v,a
    proj_gemm<<<RTOT/128, blk>>>(text,   fc1W, fc1b, 300, 0);
    proj_gemm<<<RTOT/128, blk>>>(visual, fc2W, fc2b, 35,  1);
    proj_gemm<<<RTOT/128, blk>>>(audio,  fc3W, fc3b, 74,  2);

    // all 18 QKV projections in one launch
    qkv_gemm<<<dim3(RTOT/128, 1, 18), blk>>>(Wq, Wk, Wv, bq, bk, bv);

    // V column sums, then all 6 attentions in one launch
    vsum_kernel<<<dim3(64, 2, 6), 64>>>();
    attn_flash<<<dim3(8, 128, 6), blk, ATTN_SMEM>>>();

    // out-proj + LN + average (two phases to avoid accumulation conflicts)
    epi_gemm<<<dim3(RTOT/128, 1, 3), blk>>>(Wd, bd, lng, lnb, 0);
    epi_gemm<<<dim3(RTOT/128, 1, 3), blk>>>(Wd, bd, lng, lnb, 1);

    // GRU input gates for all 6 directions in one launch
    gx_gemm<<<dim3(RTOT/128, 3, 6), blk>>>(gbih);

    // recurrence, pooling, head
    gru_kernel<<<384, 384>>>(gbhh);
    combine_kernel<<<64, 384>>>();
    head_kernel<<<64, 256>>>(fW1, fb1, bng, bnb, fW2, fb2, out);
}